// round 13
// baseline (speedup 1.0000x reference)
#include <cuda_runtime.h>
#include <cuda_fp16.h>
#include <cstdint>

// ============================================================
// y[m,n] = (sum_k x[m,k]*sign[n,k]) * scale[n] + bias[n]
// M=8192, N=4096, K=4096, fp32 in/out.
// sm_103 base target (no tcgen05) -> mma.sync.m16n8k16 fp16.
// R13: empirically-best R3 config (BM=BN=128, 256 thr, warp
// 64x32, 3 stages, 2 CTAs/SM) + single barrier per k-tile +
// bubble-fill cp.async ordering + hoisted addressing.
// ============================================================

static constexpr int MM = 8192;
static constexpr int NN = 4096;
static constexpr int KK = 4096;

static constexpr int BM = 128;
static constexpr int BN = 128;
static constexpr int BK = 64;               // 64 fp16 = 128B rows (8x16B chunks)
static constexpr int STAGES = 3;
static constexpr int KT = KK / BK;          // 64
static constexpr int NTHREADS = 256;

static constexpr int A_STAGE_BYTES = BM * BK * 2;   // 16384
static constexpr int B_STAGE_BYTES = BN * BK * 2;   // 16384
static constexpr int STAGE_BYTES = A_STAGE_BYTES + B_STAGE_BYTES; // 32768
static constexpr int SMEM_TOTAL = STAGES * STAGE_BYTES;           // 98304 -> 2 CTAs/SM

// fp16 scratch (device globals: allocation-free per harness rules)
__device__ __half g_xh[(size_t)MM * KK];    // 64 MB
__device__ __half g_wh[(size_t)NN * KK];    // 32 MB

// ---------------- PTX helpers ----------------
__device__ __forceinline__ uint32_t smem_u32(const void* p) {
    uint32_t a;
    asm("{ .reg .u64 t; cvta.to.shared.u64 t, %1; cvt.u32.u64 %0, t; }"
        : "=r"(a) : "l"(p));
    return a;
}

#define CP_ASYNC16(smem, gmem) \
    asm volatile("cp.async.cg.shared.global [%0], [%1], 16;" \
                 :: "r"(smem), "l"(gmem) : "memory")
#define CP_COMMIT() asm volatile("cp.async.commit_group;" ::: "memory")
#define CP_WAIT(n)  asm volatile("cp.async.wait_group %0;" :: "n"(n) : "memory")

__device__ __forceinline__ void ldsm4(uint32_t* r, uint32_t addr) {
    asm volatile("ldmatrix.sync.aligned.m8n8.x4.shared.b16 {%0,%1,%2,%3}, [%4];"
                 : "=r"(r[0]), "=r"(r[1]), "=r"(r[2]), "=r"(r[3]) : "r"(addr));
}

__device__ __forceinline__ void mma16816(float* d, const uint32_t* a,
                                         const uint32_t* b) {
    asm volatile(
        "mma.sync.aligned.m16n8k16.row.col.f32.f16.f16.f32 "
        "{%0,%1,%2,%3}, {%4,%5,%6,%7}, {%8,%9}, {%0,%1,%2,%3};"
        : "+f"(d[0]), "+f"(d[1]), "+f"(d[2]), "+f"(d[3])
        : "r"(a[0]), "r"(a[1]), "r"(a[2]), "r"(a[3]), "r"(b[0]), "r"(b[1]));
}

// ---------------- kernels ----------------

// fp32 -> fp16 conversion of x and sign into device scratch
__global__ void cvt_kernel(const float4* __restrict__ x,
                           const float4* __restrict__ w) {
    long long i = (long long)blockIdx.x * blockDim.x + threadIdx.x;
    const long long nx = (long long)MM * KK / 4;
    const long long nw = (long long)NN * KK / 4;
    if (i < nx) {
        float4 v = x[i];
        __half2 a = __floats2half2_rn(v.x, v.y);
        __half2 b = __floats2half2_rn(v.z, v.w);
        uint2 u;
        u.x = *reinterpret_cast<const unsigned*>(&a);
        u.y = *reinterpret_cast<const unsigned*>(&b);
        reinterpret_cast<uint2*>(g_xh)[i] = u;
    } else if (i < nx + nw) {
        long long j = i - nx;
        float4 v = w[j];
        __half2 a = __floats2half2_rn(v.x, v.y);
        __half2 b = __floats2half2_rn(v.z, v.w);
        uint2 u;
        u.x = *reinterpret_cast<const unsigned*>(&a);
        u.y = *reinterpret_cast<const unsigned*>(&b);
        reinterpret_cast<uint2*>(g_wh)[j] = u;
    }
}

__global__ void __launch_bounds__(NTHREADS, 2) gemm_kernel(
    float* __restrict__ out,
    const float* __restrict__ scale,
    const float* __restrict__ bias)
{
    extern __shared__ char smem[];
    const uint32_t sb = smem_u32(smem);
    const int tid = threadIdx.x;
    const int wid = tid >> 5;
    const int lane = tid & 31;
    const int warp_m = wid & 1;    // 2 warps over M (64 rows each)
    const int warp_n = wid >> 1;   // 4 warps over N (32 cols each)

    // L2-friendly raster: GROUP_M=8 supertiles
    constexpr int NT2 = NN / BN;   // 32
    constexpr int GROUP = 8;
    const int bid = blockIdx.x;
    const int tpg = GROUP * NT2;   // 256
    const int g = bid / tpg;
    const int r = bid % tpg;
    const int mt = g * GROUP + (r % GROUP);
    const int nt = r / GROUP;
    const int m0 = mt * BM;
    const int n0 = nt * BN;

    // cp.async addressing. idx = tid + t*256:
    //   row = (tid>>3) + t*32 (step 32 == 0 mod 8 -> XOR invariant in t)
    //   ch  = tid&7 (constant in t)
    const int c_row = tid >> 3;        // 0..31
    const int c_ch  = tid & 7;
    const uint32_t c_soff0 =
        (uint32_t)(c_row * 128 + ((c_ch ^ (c_row & 7)) << 4));
    const uint64_t a_g0 = __cvta_generic_to_global(
        g_xh + (size_t)(m0 + c_row) * KK + c_ch * 8);
    const uint64_t b_g0 = __cvta_generic_to_global(
        g_wh + (size_t)(n0 + c_row) * KK + c_ch * 8);
    constexpr uint64_t G_T = (uint64_t)32 * KK * 2;   // bytes per t-step
    constexpr uint32_t S_T = 32 * 128;                 // smem bytes per t-step

    // prologue: fill stages 0..STAGES-2
    #pragma unroll
    for (int s = 0; s < STAGES - 1; s++) {
        const uint32_t sbase = sb + s * STAGE_BYTES;
        const uint64_t koff = (uint64_t)s * BK * 2;
        #pragma unroll
        for (int t = 0; t < 4; t++)       // A: 128 rows
            CP_ASYNC16(sbase + c_soff0 + t * S_T, a_g0 + t * G_T + koff);
        #pragma unroll
        for (int t = 0; t < 4; t++)       // B: 128 rows
            CP_ASYNC16(sbase + A_STAGE_BYTES + c_soff0 + t * S_T,
                       b_g0 + t * G_T + koff);
        CP_COMMIT();
    }

    float acc[4][4][4];
    #pragma unroll
    for (int mi = 0; mi < 4; mi++)
        #pragma unroll
        for (int ni = 0; ni < 4; ni++)
            #pragma unroll
            for (int e = 0; e < 4; e++)
                acc[mi][ni][e] = 0.f;

    // LDSM addressing (row step 16 == 0 mod 8 -> XOR invariant)
    const int lrow = lane & 15;
    const int khalf = lane >> 4;
    const int a_row = warp_m * 64 + lrow;
    const int b_row = warp_n * 32 + lrow;
    const uint32_t a_row0 = (uint32_t)(a_row * 128);
    const uint32_t a_xor0 = (uint32_t)((a_row & 7) << 4);
    const uint32_t b_row0 = (uint32_t)(b_row * 128) + A_STAGE_BYTES;
    const uint32_t b_xor0 = (uint32_t)((b_row & 7) << 4);

    // helper: load B fragments for one ks-group (2 LDSM.x4 -> 4 n8 frags)
    auto load_b = [&](uint32_t sbase, uint32_t chb, uint32_t (*bfr)[2]) {
        #pragma unroll
        for (int nb = 0; nb < 2; nb++) {
            uint32_t t4[4];
            ldsm4(t4, sbase + b_row0 + nb * 2048 + (chb ^ b_xor0));
            bfr[nb * 2 + 0][0] = t4[0]; bfr[nb * 2 + 0][1] = t4[2];
            bfr[nb * 2 + 1][0] = t4[1]; bfr[nb * 2 + 1][1] = t4[3];
        }
    };

    #pragma unroll 1
    for (int kt = 0; kt < KT; kt++) {
        CP_WAIT(STAGES - 2);
        __syncthreads();   // single barrier per k-tile: LDSM results of
        // iter kt-1 are register-consumed before warps reach this barrier,
        // so it also orders compute(kt-1) before cp.async overwrite below.

        const uint32_t sbase = sb + (kt % STAGES) * STAGE_BYTES;

        // --- ks = 0: start fragment loads first ---
        const uint32_t chb0 = (uint32_t)(khalf << 4);
        uint32_t bfr[4][2];
        load_b(sbase, chb0, bfr);
        uint32_t afr0[4][4];
        #pragma unroll
        for (int mi = 0; mi < 4; mi++)
            ldsm4(afr0[mi], sbase + a_row0 + mi * 2048 + (chb0 ^ a_xor0));

        // --- overlap: issue next-stage cp.async during LDSM latency ---
        const int ktl = kt + STAGES - 1;
        if (ktl < KT) {
            const int s = ktl % STAGES;
            const uint32_t lbase = sb + s * STAGE_BYTES;
            const uint64_t koff = (uint64_t)ktl * BK * 2;
            #pragma unroll
            for (int t = 0; t < 4; t++)
                CP_ASYNC16(lbase + c_soff0 + t * S_T, a_g0 + t * G_T + koff);
            #pragma unroll
            for (int t = 0; t < 4; t++)
                CP_ASYNC16(lbase + A_STAGE_BYTES + c_soff0 + t * S_T,
                           b_g0 + t * G_T + koff);
        }
        CP_COMMIT();

        // --- ks = 0 MMAs ---
        #pragma unroll
        for (int mi = 0; mi < 4; mi++)
            #pragma unroll
            for (int ni = 0; ni < 4; ni++)
                mma16816(acc[mi][ni], afr0[mi], bfr[ni]);

        // --- ks = 1..3 ---
        #pragma unroll
        for (int ks = 1; ks < BK / 16; ks++) {
            const uint32_t chb = (uint32_t)((ks * 2 + khalf) << 4);
            load_b(sbase, chb, bfr);
            #pragma unroll
            for (int mi = 0; mi < 4; mi++) {
                uint32_t afr[4];
                ldsm4(afr, sbase + a_row0 + mi * 2048 + (chb ^ a_xor0));
                #pragma unroll
                for (int ni = 0; ni < 4; ni++)
                    mma16816(acc[mi][ni], afr, bfr[ni]);
            }
        }
        // no bottom barrier (see comment at top barrier)
    }

    // Epilogue: scale+bias, float2 stores (quad = 32B sector)
    const int colbase = n0 + warp_n * 32 + (lane & 3) * 2;
    const int rowbase = m0 + warp_m * 64 + (lane >> 2);

    float2 sc2[4], bi2[4];
    #pragma unroll
    for (int ni = 0; ni < 4; ni++) {
        const int c = colbase + ni * 8;
        sc2[ni] = *reinterpret_cast<const float2*>(scale + c);
        bi2[ni] = *reinterpret_cast<const float2*>(bias + c);
    }

    #pragma unroll
    for (int mi = 0; mi < 4; mi++) {
        const int r0 = rowbase + mi * 16;
        #pragma unroll
        for (int ni = 0; ni < 4; ni++) {
            const int c = colbase + ni * 8;
            float2 v0, v1;
            v0.x = acc[mi][ni][0] * sc2[ni].x + bi2[ni].x;
            v0.y = acc[mi][ni][1] * sc2[ni].y + bi2[ni].y;
            v1.x = acc[mi][ni][2] * sc2[ni].x + bi2[ni].x;
            v1.y = acc[mi][ni][3] * sc2[ni].y + bi2[ni].y;
            *reinterpret_cast<float2*>(out + (size_t)r0 * NN + c) = v0;
            *reinterpret_cast<float2*>(out + (size_t)(r0 + 8) * NN + c) = v1;
        }
    }
}

// ---------------- host launch ----------------
extern "C" void kernel_launch(void* const* d_in, const int* in_sizes, int n_in,
                              void* d_out, int out_size) {
    const float* x  = (const float*)d_in[0];  // (B,S,IN)  8192 x 4096
    const float* w  = (const float*)d_in[1];  // (OUT,IN)  4096 x 4096
    const float* sc = (const float*)d_in[2];  // (OUT,)
    const float* bi = (const float*)d_in[3];  // (OUT,)
    float* out = (float*)d_out;

    cudaFuncSetAttribute(gemm_kernel, cudaFuncAttributeMaxDynamicSharedMemorySize,
                         SMEM_TOTAL);

    // 1) convert fp32 -> fp16 scratch
    const long long tot4 = ((long long)MM * KK + (long long)NN * KK) / 4;
    const int cvt_blocks = (int)((tot4 + 255) / 256);
    cvt_kernel<<<cvt_blocks, 256>>>((const float4*)x, (const float4*)w);

    // 2) HMMA GEMM + fused scale/bias epilogue
    const int grid = (MM / BM) * (NN / BN);  // 2048 CTAs
    gemm_kernel<<<grid, NTHREADS, SMEM_TOTAL>>>(out, sc, bi);
}

// round 14
// speedup vs baseline: 1.4962x; 1.4962x over previous
#include <cuda_runtime.h>
#include <cuda_fp16.h>
#include <cstdint>

// ============================================================
// y[m,n] = (sum_k x[m,k]*sign[n,k]) * scale[n] + bias[n]
// M=8192, N=4096, K=4096, fp32 in/out.
// sm_103 base target (no tcgen05) -> mma.sync.m16n8k16 fp16.
// R14 == R3 verbatim (best passing config, 768us): BM=BN=128,
// 256 thr, warp 64x32, 3-stage cp.async, two barriers per kt.
// ============================================================

static constexpr int MM = 8192;
static constexpr int NN = 4096;
static constexpr int KK = 4096;

static constexpr int BM = 128;
static constexpr int BN = 128;
static constexpr int BK = 64;               // 64 fp16 = 128B rows (8x16B chunks)
static constexpr int STAGES = 3;
static constexpr int KT = KK / BK;          // 64

static constexpr int A_STAGE_BYTES = BM * BK * 2;   // 16384
static constexpr int B_STAGE_BYTES = BN * BK * 2;   // 16384
static constexpr int STAGE_BYTES = A_STAGE_BYTES + B_STAGE_BYTES; // 32768
static constexpr int SMEM_TOTAL = STAGES * STAGE_BYTES;           // 98304

// fp16 scratch (device globals: allocation-free per harness rules)
__device__ __half g_xh[(size_t)MM * KK];    // 64 MB
__device__ __half g_wh[(size_t)NN * KK];    // 32 MB

// ---------------- PTX helpers ----------------
__device__ __forceinline__ uint32_t smem_u32(const void* p) {
    uint32_t a;
    asm("{ .reg .u64 t; cvta.to.shared.u64 t, %1; cvt.u32.u64 %0, t; }"
        : "=r"(a) : "l"(p));
    return a;
}

#define CP_ASYNC16(smem, gmem) \
    asm volatile("cp.async.cg.shared.global [%0], [%1], 16;" \
                 :: "r"(smem), "l"(gmem) : "memory")
#define CP_COMMIT() asm volatile("cp.async.commit_group;" ::: "memory")
#define CP_WAIT(n)  asm volatile("cp.async.wait_group %0;" :: "n"(n) : "memory")

__device__ __forceinline__ void ldsm4(uint32_t* r, uint32_t addr) {
    asm volatile("ldmatrix.sync.aligned.m8n8.x4.shared.b16 {%0,%1,%2,%3}, [%4];"
                 : "=r"(r[0]), "=r"(r[1]), "=r"(r[2]), "=r"(r[3]) : "r"(addr));
}

__device__ __forceinline__ void mma16816(float* d, const uint32_t* a,
                                         const uint32_t* b) {
    asm volatile(
        "mma.sync.aligned.m16n8k16.row.col.f32.f16.f16.f32 "
        "{%0,%1,%2,%3}, {%4,%5,%6,%7}, {%8,%9}, {%0,%1,%2,%3};"
        : "+f"(d[0]), "+f"(d[1]), "+f"(d[2]), "+f"(d[3])
        : "r"(a[0]), "r"(a[1]), "r"(a[2]), "r"(a[3]), "r"(b[0]), "r"(b[1]));
}

// XOR swizzle: 128B rows of 8 x 16B chunks, chunk ^= (row & 7)
__device__ __forceinline__ uint32_t sw_off(int row, int chunk) {
    return (uint32_t)(row * 128 + ((chunk ^ (row & 7)) << 4));
}

// ---------------- kernels ----------------

// fp32 -> fp16 conversion of x and sign into device scratch
__global__ void cvt_kernel(const float4* __restrict__ x,
                           const float4* __restrict__ w) {
    long long i = (long long)blockIdx.x * blockDim.x + threadIdx.x;
    const long long nx = (long long)MM * KK / 4;
    const long long nw = (long long)NN * KK / 4;
    if (i < nx) {
        float4 v = x[i];
        __half2 a = __floats2half2_rn(v.x, v.y);
        __half2 b = __floats2half2_rn(v.z, v.w);
        uint2 u;
        u.x = *reinterpret_cast<const unsigned*>(&a);
        u.y = *reinterpret_cast<const unsigned*>(&b);
        reinterpret_cast<uint2*>(g_xh)[i] = u;
    } else if (i < nx + nw) {
        long long j = i - nx;
        float4 v = w[j];
        __half2 a = __floats2half2_rn(v.x, v.y);
        __half2 b = __floats2half2_rn(v.z, v.w);
        uint2 u;
        u.x = *reinterpret_cast<const unsigned*>(&a);
        u.y = *reinterpret_cast<const unsigned*>(&b);
        reinterpret_cast<uint2*>(g_wh)[j] = u;
    }
}

__global__ void __launch_bounds__(256, 2) gemm_kernel(
    float* __restrict__ out,
    const float* __restrict__ scale,
    const float* __restrict__ bias)
{
    extern __shared__ char smem[];
    const uint32_t sb = smem_u32(smem);
    const int tid = threadIdx.x;
    const int wid = tid >> 5;
    const int lane = tid & 31;
    const int warp_m = wid & 1;    // 2 warps over M (64 rows each)
    const int warp_n = wid >> 1;   // 4 warps over N (32 cols each)

    // L2-friendly raster: GROUP_M=8 supertiles
    constexpr int NT2 = NN / BN;   // 32
    constexpr int GROUP = 8;
    const int bid = blockIdx.x;
    const int tpg = GROUP * NT2;   // 256 (~one 2-CTA/SM wave)
    const int g = bid / tpg;
    const int r = bid % tpg;
    const int mt = g * GROUP + (r % GROUP);
    const int nt = r / GROUP;
    const int m0 = mt * BM;
    const int n0 = nt * BN;

    // per-thread cp.async mapping: 1024 16B-chunks per operand, 4 per thread
    // idx = tid + t*256 ; row = idx>>3 (0..127), chunk = idx&7
    uint64_t a_gbase[4], b_gbase[4];
    uint32_t a_soff[4], b_soff[4];
    #pragma unroll
    for (int t = 0; t < 4; t++) {
        int idx = tid + t * 256;
        int row = idx >> 3;
        int ch  = idx & 7;
        a_gbase[t] = __cvta_generic_to_global(
            g_xh + (size_t)(m0 + row) * KK + ch * 8);
        b_gbase[t] = __cvta_generic_to_global(
            g_wh + (size_t)(n0 + row) * KK + ch * 8);
        a_soff[t] = sw_off(row, ch);
        b_soff[t] = sw_off(row, ch) + A_STAGE_BYTES;
    }

    // prologue: fill stages 0..STAGES-2
    #pragma unroll
    for (int s = 0; s < STAGES - 1; s++) {
        const uint32_t sbase = sb + s * STAGE_BYTES;
        const uint64_t koff = (uint64_t)s * BK * 2;  // byte offset along K
        #pragma unroll
        for (int t = 0; t < 4; t++) {
            CP_ASYNC16(sbase + a_soff[t], a_gbase[t] + koff);
            CP_ASYNC16(sbase + b_soff[t], b_gbase[t] + koff);
        }
        CP_COMMIT();
    }

    float acc[4][4][4];
    #pragma unroll
    for (int mi = 0; mi < 4; mi++)
        #pragma unroll
        for (int ni = 0; ni < 4; ni++)
            #pragma unroll
            for (int e = 0; e < 4; e++)
                acc[mi][ni][e] = 0.f;

    // ldmatrix per-lane row index within a 16-row block, and chunk parity
    const int lrow = lane & 15;          // rows 0..15
    const int khalf = lane >> 4;         // 0: k0-7 chunk, 1: k8-15 chunk

    #pragma unroll 1
    for (int kt = 0; kt < KT; kt++) {
        CP_WAIT(STAGES - 2);
        __syncthreads();

        // issue loads for k-tile kt+STAGES-1
        const int ktl = kt + STAGES - 1;
        if (ktl < KT) {
            const int s = ktl % STAGES;
            const uint32_t sbase = sb + s * STAGE_BYTES;
            const uint64_t koff = (uint64_t)ktl * BK * 2;
            #pragma unroll
            for (int t = 0; t < 4; t++) {
                CP_ASYNC16(sbase + a_soff[t], a_gbase[t] + koff);
                CP_ASYNC16(sbase + b_soff[t], b_gbase[t] + koff);
            }
        }
        CP_COMMIT();

        // compute on stage kt % STAGES
        const uint32_t abase = sb + (kt % STAGES) * STAGE_BYTES;
        const uint32_t bbase = abase + A_STAGE_BYTES;

        #pragma unroll
        for (int ks = 0; ks < BK / 16; ks++) {
            const int ch = ks * 2 + khalf;   // this lane's 16B chunk along K

            uint32_t afr[4][4];
            #pragma unroll
            for (int mi = 0; mi < 4; mi++) {
                const int row = warp_m * 64 + mi * 16 + lrow;
                ldsm4(afr[mi], abase + sw_off(row, ch));
            }
            uint32_t bfr[4][2];
            #pragma unroll
            for (int nb = 0; nb < 2; nb++) {
                const int row = warp_n * 32 + nb * 16 + lrow;
                uint32_t t4[4];
                ldsm4(t4, bbase + sw_off(row, ch));
                bfr[nb * 2 + 0][0] = t4[0]; bfr[nb * 2 + 0][1] = t4[2];
                bfr[nb * 2 + 1][0] = t4[1]; bfr[nb * 2 + 1][1] = t4[3];
            }
            #pragma unroll
            for (int mi = 0; mi < 4; mi++)
                #pragma unroll
                for (int ni = 0; ni < 4; ni++)
                    mma16816(acc[mi][ni], afr[mi], bfr[ni]);
        }
        __syncthreads();
    }

    // Epilogue: scale+bias, direct stores (each quad writes a 32B sector)
    const int colbase = n0 + warp_n * 32 + (lane & 3) * 2;
    const int rowbase = m0 + warp_m * 64 + (lane >> 2);

    float2 sc2[4], bi2[4];
    #pragma unroll
    for (int ni = 0; ni < 4; ni++) {
        const int c = colbase + ni * 8;
        sc2[ni] = *reinterpret_cast<const float2*>(scale + c);
        bi2[ni] = *reinterpret_cast<const float2*>(bias + c);
    }

    #pragma unroll
    for (int mi = 0; mi < 4; mi++) {
        const int r0 = rowbase + mi * 16;
        #pragma unroll
        for (int ni = 0; ni < 4; ni++) {
            const int c = colbase + ni * 8;
            float2 v0, v1;
            v0.x = acc[mi][ni][0] * sc2[ni].x + bi2[ni].x;
            v0.y = acc[mi][ni][1] * sc2[ni].y + bi2[ni].y;
            v1.x = acc[mi][ni][2] * sc2[ni].x + bi2[ni].x;
            v1.y = acc[mi][ni][3] * sc2[ni].y + bi2[ni].y;
            *reinterpret_cast<float2*>(out + (size_t)r0 * NN + c) = v0;
            *reinterpret_cast<float2*>(out + (size_t)(r0 + 8) * NN + c) = v1;
        }
    }
}

// ---------------- host launch ----------------
extern "C" void kernel_launch(void* const* d_in, const int* in_sizes, int n_in,
                              void* d_out, int out_size) {
    const float* x  = (const float*)d_in[0];  // (B,S,IN)  8192 x 4096
    const float* w  = (const float*)d_in[1];  // (OUT,IN)  4096 x 4096
    const float* sc = (const float*)d_in[2];  // (OUT,)
    const float* bi = (const float*)d_in[3];  // (OUT,)
    float* out = (float*)d_out;

    cudaFuncSetAttribute(gemm_kernel, cudaFuncAttributeMaxDynamicSharedMemorySize,
                         SMEM_TOTAL);

    // 1) convert fp32 -> fp16 scratch
    const long long tot4 = ((long long)MM * KK + (long long)NN * KK) / 4;
    const int cvt_blocks = (int)((tot4 + 255) / 256);
    cvt_kernel<<<cvt_blocks, 256>>>((const float4*)x, (const float4*)w);

    // 2) HMMA GEMM + fused scale/bias epilogue
    const int grid = (MM / BM) * (NN / BN);  // 2048 CTAs
    gemm_kernel<<<grid, 256, SMEM_TOTAL>>>(out, sc, bi);
}

// round 15
// speedup vs baseline: 1.5126x; 1.0110x over previous
#include <cuda_runtime.h>
#include <cuda_fp16.h>
#include <cstdint>

// ============================================================
// y[m,n] = (sum_k x[m,k]*sign[n,k]) * scale[n] + bias[n]
// M=8192, N=4096, K=4096, fp32 in/out.
// sm_103 base target (no tcgen05) -> mma.sync.m16n8k16 fp16.
// R15: R3/R14 GEMM verbatim (720us = legacy-HMMA HW floor) +
// widened cvt kernel (8 floats -> one 16B store per thread).
// ============================================================

static constexpr int MM = 8192;
static constexpr int NN = 4096;
static constexpr int KK = 4096;

static constexpr int BM = 128;
static constexpr int BN = 128;
static constexpr int BK = 64;               // 64 fp16 = 128B rows (8x16B chunks)
static constexpr int STAGES = 3;
static constexpr int KT = KK / BK;          // 64

static constexpr int A_STAGE_BYTES = BM * BK * 2;   // 16384
static constexpr int B_STAGE_BYTES = BN * BK * 2;   // 16384
static constexpr int STAGE_BYTES = A_STAGE_BYTES + B_STAGE_BYTES; // 32768
static constexpr int SMEM_TOTAL = STAGES * STAGE_BYTES;           // 98304

// fp16 scratch (device globals: allocation-free per harness rules)
__device__ __half g_xh[(size_t)MM * KK];    // 64 MB
__device__ __half g_wh[(size_t)NN * KK];    // 32 MB

// ---------------- PTX helpers ----------------
__device__ __forceinline__ uint32_t smem_u32(const void* p) {
    uint32_t a;
    asm("{ .reg .u64 t; cvta.to.shared.u64 t, %1; cvt.u32.u64 %0, t; }"
        : "=r"(a) : "l"(p));
    return a;
}

#define CP_ASYNC16(smem, gmem) \
    asm volatile("cp.async.cg.shared.global [%0], [%1], 16;" \
                 :: "r"(smem), "l"(gmem) : "memory")
#define CP_COMMIT() asm volatile("cp.async.commit_group;" ::: "memory")
#define CP_WAIT(n)  asm volatile("cp.async.wait_group %0;" :: "n"(n) : "memory")

__device__ __forceinline__ void ldsm4(uint32_t* r, uint32_t addr) {
    asm volatile("ldmatrix.sync.aligned.m8n8.x4.shared.b16 {%0,%1,%2,%3}, [%4];"
                 : "=r"(r[0]), "=r"(r[1]), "=r"(r[2]), "=r"(r[3]) : "r"(addr));
}

__device__ __forceinline__ void mma16816(float* d, const uint32_t* a,
                                         const uint32_t* b) {
    asm volatile(
        "mma.sync.aligned.m16n8k16.row.col.f32.f16.f16.f32 "
        "{%0,%1,%2,%3}, {%4,%5,%6,%7}, {%8,%9}, {%0,%1,%2,%3};"
        : "+f"(d[0]), "+f"(d[1]), "+f"(d[2]), "+f"(d[3])
        : "r"(a[0]), "r"(a[1]), "r"(a[2]), "r"(a[3]), "r"(b[0]), "r"(b[1]));
}

// XOR swizzle: 128B rows of 8 x 16B chunks, chunk ^= (row & 7)
__device__ __forceinline__ uint32_t sw_off(int row, int chunk) {
    return (uint32_t)(row * 128 + ((chunk ^ (row & 7)) << 4));
}

// ---------------- kernels ----------------

// fp32 -> fp16 conversion, 8 floats per thread, 16B stores.
__global__ void cvt_kernel(const float4* __restrict__ x,
                           const float4* __restrict__ w) {
    const long long i = (long long)blockIdx.x * blockDim.x + threadIdx.x;
    const long long nx8 = (long long)MM * KK / 8;   // x in 8-float units
    const long long nw8 = (long long)NN * KK / 8;   // w in 8-float units
    if (i < nx8) {
        const float4 v0 = x[i * 2];
        const float4 v1 = x[i * 2 + 1];
        const __half2 a = __floats2half2_rn(v0.x, v0.y);
        const __half2 b = __floats2half2_rn(v0.z, v0.w);
        const __half2 c = __floats2half2_rn(v1.x, v1.y);
        const __half2 d = __floats2half2_rn(v1.z, v1.w);
        uint4 u;
        u.x = *reinterpret_cast<const unsigned*>(&a);
        u.y = *reinterpret_cast<const unsigned*>(&b);
        u.z = *reinterpret_cast<const unsigned*>(&c);
        u.w = *reinterpret_cast<const unsigned*>(&d);
        reinterpret_cast<uint4*>(g_xh)[i] = u;
    } else if (i < nx8 + nw8) {
        const long long j = i - nx8;
        const float4 v0 = w[j * 2];
        const float4 v1 = w[j * 2 + 1];
        const __half2 a = __floats2half2_rn(v0.x, v0.y);
        const __half2 b = __floats2half2_rn(v0.z, v0.w);
        const __half2 c = __floats2half2_rn(v1.x, v1.y);
        const __half2 d = __floats2half2_rn(v1.z, v1.w);
        uint4 u;
        u.x = *reinterpret_cast<const unsigned*>(&a);
        u.y = *reinterpret_cast<const unsigned*>(&b);
        u.z = *reinterpret_cast<const unsigned*>(&c);
        u.w = *reinterpret_cast<const unsigned*>(&d);
        reinterpret_cast<uint4*>(g_wh)[j] = u;
    }
}

__global__ void __launch_bounds__(256, 2) gemm_kernel(
    float* __restrict__ out,
    const float* __restrict__ scale,
    const float* __restrict__ bias)
{
    extern __shared__ char smem[];
    const uint32_t sb = smem_u32(smem);
    const int tid = threadIdx.x;
    const int wid = tid >> 5;
    const int lane = tid & 31;
    const int warp_m = wid & 1;    // 2 warps over M (64 rows each)
    const int warp_n = wid >> 1;   // 4 warps over N (32 cols each)

    // L2-friendly raster: GROUP_M=8 supertiles
    constexpr int NT2 = NN / BN;   // 32
    constexpr int GROUP = 8;
    const int bid = blockIdx.x;
    const int tpg = GROUP * NT2;   // 256 (~one 2-CTA/SM wave)
    const int g = bid / tpg;
    const int r = bid % tpg;
    const int mt = g * GROUP + (r % GROUP);
    const int nt = r / GROUP;
    const int m0 = mt * BM;
    const int n0 = nt * BN;

    // per-thread cp.async mapping: 1024 16B-chunks per operand, 4 per thread
    // idx = tid + t*256 ; row = idx>>3 (0..127), chunk = idx&7
    uint64_t a_gbase[4], b_gbase[4];
    uint32_t a_soff[4], b_soff[4];
    #pragma unroll
    for (int t = 0; t < 4; t++) {
        int idx = tid + t * 256;
        int row = idx >> 3;
        int ch  = idx & 7;
        a_gbase[t] = __cvta_generic_to_global(
            g_xh + (size_t)(m0 + row) * KK + ch * 8);
        b_gbase[t] = __cvta_generic_to_global(
            g_wh + (size_t)(n0 + row) * KK + ch * 8);
        a_soff[t] = sw_off(row, ch);
        b_soff[t] = sw_off(row, ch) + A_STAGE_BYTES;
    }

    // prologue: fill stages 0..STAGES-2
    #pragma unroll
    for (int s = 0; s < STAGES - 1; s++) {
        const uint32_t sbase = sb + s * STAGE_BYTES;
        const uint64_t koff = (uint64_t)s * BK * 2;  // byte offset along K
        #pragma unroll
        for (int t = 0; t < 4; t++) {
            CP_ASYNC16(sbase + a_soff[t], a_gbase[t] + koff);
            CP_ASYNC16(sbase + b_soff[t], b_gbase[t] + koff);
        }
        CP_COMMIT();
    }

    float acc[4][4][4];
    #pragma unroll
    for (int mi = 0; mi < 4; mi++)
        #pragma unroll
        for (int ni = 0; ni < 4; ni++)
            #pragma unroll
            for (int e = 0; e < 4; e++)
                acc[mi][ni][e] = 0.f;

    // ldmatrix per-lane row index within a 16-row block, and chunk parity
    const int lrow = lane & 15;          // rows 0..15
    const int khalf = lane >> 4;         // 0: k0-7 chunk, 1: k8-15 chunk

    #pragma unroll 1
    for (int kt = 0; kt < KT; kt++) {
        CP_WAIT(STAGES - 2);
        __syncthreads();

        // issue loads for k-tile kt+STAGES-1
        const int ktl = kt + STAGES - 1;
        if (ktl < KT) {
            const int s = ktl % STAGES;
            const uint32_t sbase = sb + s * STAGE_BYTES;
            const uint64_t koff = (uint64_t)ktl * BK * 2;
            #pragma unroll
            for (int t = 0; t < 4; t++) {
                CP_ASYNC16(sbase + a_soff[t], a_gbase[t] + koff);
                CP_ASYNC16(sbase + b_soff[t], b_gbase[t] + koff);
            }
        }
        CP_COMMIT();

        // compute on stage kt % STAGES
        const uint32_t abase = sb + (kt % STAGES) * STAGE_BYTES;
        const uint32_t bbase = abase + A_STAGE_BYTES;

        #pragma unroll
        for (int ks = 0; ks < BK / 16; ks++) {
            const int ch = ks * 2 + khalf;   // this lane's 16B chunk along K

            uint32_t afr[4][4];
            #pragma unroll
            for (int mi = 0; mi < 4; mi++) {
                const int row = warp_m * 64 + mi * 16 + lrow;
                ldsm4(afr[mi], abase + sw_off(row, ch));
            }
            uint32_t bfr[4][2];
            #pragma unroll
            for (int nb = 0; nb < 2; nb++) {
                const int row = warp_n * 32 + nb * 16 + lrow;
                uint32_t t4[4];
                ldsm4(t4, bbase + sw_off(row, ch));
                bfr[nb * 2 + 0][0] = t4[0]; bfr[nb * 2 + 0][1] = t4[2];
                bfr[nb * 2 + 1][0] = t4[1]; bfr[nb * 2 + 1][1] = t4[3];
            }
            #pragma unroll
            for (int mi = 0; mi < 4; mi++)
                #pragma unroll
                for (int ni = 0; ni < 4; ni++)
                    mma16816(acc[mi][ni], afr[mi], bfr[ni]);
        }
        __syncthreads();
    }

    // Epilogue: scale+bias, direct stores (each quad writes a 32B sector)
    const int colbase = n0 + warp_n * 32 + (lane & 3) * 2;
    const int rowbase = m0 + warp_m * 64 + (lane >> 2);

    float2 sc2[4], bi2[4];
    #pragma unroll
    for (int ni = 0; ni < 4; ni++) {
        const int c = colbase + ni * 8;
        sc2[ni] = *reinterpret_cast<const float2*>(scale + c);
        bi2[ni] = *reinterpret_cast<const float2*>(bias + c);
    }

    #pragma unroll
    for (int mi = 0; mi < 4; mi++) {
        const int r0 = rowbase + mi * 16;
        #pragma unroll
        for (int ni = 0; ni < 4; ni++) {
            const int c = colbase + ni * 8;
            float2 v0, v1;
            v0.x = acc[mi][ni][0] * sc2[ni].x + bi2[ni].x;
            v0.y = acc[mi][ni][1] * sc2[ni].y + bi2[ni].y;
            v1.x = acc[mi][ni][2] * sc2[ni].x + bi2[ni].x;
            v1.y = acc[mi][ni][3] * sc2[ni].y + bi2[ni].y;
            *reinterpret_cast<float2*>(out + (size_t)r0 * NN + c) = v0;
            *reinterpret_cast<float2*>(out + (size_t)(r0 + 8) * NN + c) = v1;
        }
    }
}

// ---------------- host launch ----------------
extern "C" void kernel_launch(void* const* d_in, const int* in_sizes, int n_in,
                              void* d_out, int out_size) {
    const float* x  = (const float*)d_in[0];  // (B,S,IN)  8192 x 4096
    const float* w  = (const float*)d_in[1];  // (OUT,IN)  4096 x 4096
    const float* sc = (const float*)d_in[2];  // (OUT,)
    const float* bi = (const float*)d_in[3];  // (OUT,)
    float* out = (float*)d_out;

    cudaFuncSetAttribute(gemm_kernel, cudaFuncAttributeMaxDynamicSharedMemorySize,
                         SMEM_TOTAL);

    // 1) convert fp32 -> fp16 scratch (8 floats / thread, 16B stores)
    const long long tot8 = ((long long)MM * KK + (long long)NN * KK) / 8;
    const int cvt_blocks = (int)((tot8 + 255) / 256);
    cvt_kernel<<<cvt_blocks, 256>>>((const float4*)x, (const float4*)w);

    // 2) HMMA GEMM + fused scale/bias epilogue
    const int grid = (MM / BM) * (NN / BN);  // 2048 CTAs
    gemm_kernel<<<grid, 256, SMEM_TOTAL>>>(out, sc, bi);
}